// round 2
// baseline (speedup 1.0000x reference)
#include <cuda_runtime.h>
#include <cuda_fp16.h>
#include <stdint.h>
#include <math.h>

// Problem: B=8,H=8 (64 bh), N=1024 tokens, D=256. out fp32.
#define N_TOK 1024
#define DIM   256
#define NBH   64
#define BM    64
#define BN    64
#define TOT   (NBH * N_TOK * DIM)   // 16,777,216 elements

// fp16 scratch (device globals: allocation-free)
__device__ __half g_Qh[TOT];
__device__ __half g_Kh[TOT];
__device__ __half g_Kl[TOT];
__device__ __half g_Vh[TOT];

// ---------------------------------------------------------------------------
// Preprocess: 2D RoPE on Q,K; convert to fp16 (K gets hi/lo split); V->fp16.
// One block per (bh*N + n) row; 128 threads = 128 complex pairs (D=256).
// ---------------------------------------------------------------------------
__global__ void __launch_bounds__(128) prep_kernel(
    const float* __restrict__ Q,
    const float* __restrict__ K,
    const float* __restrict__ V)
{
    int row = blockIdx.x;            // bh*1024 + n
    int i   = threadIdx.x;           // pair index 0..127
    int n   = row & (N_TOK - 1);
    // first 64 pairs use x = n%32, last 64 use y = n/32
    float pos = (i < 64) ? (float)(n & 31) : (float)(n >> 5);
    float e   = (float)(i & 63);
    // 10000^(-e/64) = 2^(-e * log2(10000)/64)
    float inv = exp2f(-0.20762050592445997f * e);
    float ang = pos * inv;           // in [0, 31]

    // range-reduce to [-pi, pi] (fast-math safe), then fast sincos
    float kq = rintf(ang * 0.15915494309189535f);
    float r  = fmaf(-kq, 6.2831854820251465f, ang);
    r        = fmaf(-kq, -1.7484555e-7f, r);
    float sa, ca;
    __sincosf(r, &sa, &ca);

    size_t base = (size_t)row * DIM + 2 * i;
    float2 q = *(const float2*)(Q + base);
    float2 k = *(const float2*)(K + base);
    float2 v = *(const float2*)(V + base);

    float q0 = q.x * ca - q.y * sa;
    float q1 = q.x * sa + q.y * ca;
    float k0 = k.x * ca - k.y * sa;
    float k1 = k.x * sa + k.y * ca;

    __half h0 = __float2half_rn(k0);
    __half h1 = __float2half_rn(k1);
    float  e0 = k0 - __half2float(h0);
    float  e1 = k1 - __half2float(h1);

    *(__half2*)(g_Qh + base) = __floats2half2_rn(q0, q1);
    *(__half2*)(g_Kh + base) = __halves2half2(h0, h1);
    *(__half2*)(g_Kl + base) = __floats2half2_rn(e0, e1);
    *(__half2*)(g_Vh + base) = __floats2half2_rn(v.x, v.y);
}

// ---------------------------------------------------------------------------
// PTX wrappers
// ---------------------------------------------------------------------------
__device__ __forceinline__ void ldsm4(uint32_t& r0, uint32_t& r1, uint32_t& r2,
                                      uint32_t& r3, uint32_t addr) {
    asm volatile("ldmatrix.sync.aligned.m8n8.x4.shared.b16 {%0,%1,%2,%3}, [%4];\n"
                 : "=r"(r0), "=r"(r1), "=r"(r2), "=r"(r3) : "r"(addr));
}
__device__ __forceinline__ void ldsm4t(uint32_t& r0, uint32_t& r1, uint32_t& r2,
                                       uint32_t& r3, uint32_t addr) {
    asm volatile("ldmatrix.sync.aligned.m8n8.x4.trans.shared.b16 {%0,%1,%2,%3}, [%4];\n"
                 : "=r"(r0), "=r"(r1), "=r"(r2), "=r"(r3) : "r"(addr));
}
__device__ __forceinline__ void mma16816(float* c,
                                         uint32_t a0, uint32_t a1, uint32_t a2, uint32_t a3,
                                         uint32_t b0, uint32_t b1) {
    asm volatile(
        "mma.sync.aligned.m16n8k16.row.col.f32.f16.f16.f32 "
        "{%0,%1,%2,%3},{%4,%5,%6,%7},{%8,%9},{%0,%1,%2,%3};\n"
        : "+f"(c[0]), "+f"(c[1]), "+f"(c[2]), "+f"(c[3])
        : "r"(a0), "r"(a1), "r"(a2), "r"(a3), "r"(b0), "r"(b1));
}
__device__ __forceinline__ void cpasync16(uint32_t sdst, const void* gsrc) {
    asm volatile("cp.async.cg.shared.global [%0], [%1], 16;\n"
                 :: "r"(sdst), "l"(gsrc) : "memory");
}
__device__ __forceinline__ float ex2f(float x) {
    float y;
    asm("ex2.approx.ftz.f32 %0, %1;" : "=f"(y) : "f"(x));
    return y;
}
__device__ __forceinline__ uint32_t packh2(float lo, float hi) {
    __half2 h = __floats2half2_rn(lo, hi);
    return *reinterpret_cast<uint32_t*>(&h);
}

// smem layout: Q tile 64x256 f16 (32 KB) + 2 buffers of {Khi,Klo,V} 32 KB each
#define SMEM_Q   32768u
#define SMEM_BUF 98304u
#define SMEM_TOT (SMEM_Q + 2u * SMEM_BUF)   // 229376

// XOR swizzle: rows are 512 B = 32 chunks of 16 B; phys chunk = c ^ (r&7)
__device__ __forceinline__ uint32_t swz(uint32_t base, int r, int c) {
    return base + ((uint32_t)r << 9) + (uint32_t)(((c ^ (r & 7))) << 4);
}

__device__ __forceinline__ void load_kv(uint32_t bb,
                                        const __half* __restrict__ gK,
                                        const __half* __restrict__ gKl,
                                        const __half* __restrict__ gV,
                                        int t, int tid) {
    int go0 = t * BN * DIM;
#pragma unroll
    for (int it = 0; it < 16; it++) {
        int idx = tid + it * 128;
        int r = idx >> 5, c = idx & 31;
        uint32_t so = ((uint32_t)r << 9) + (uint32_t)(((c ^ (r & 7))) << 4);
        int go = go0 + r * DIM + c * 8;
        cpasync16(bb + so,           gK  + go);
        cpasync16(bb + 32768u + so,  gKl + go);
        cpasync16(bb + 65536u + so,  gV  + go);
    }
}

// ---------------------------------------------------------------------------
// Flash attention: CTA = (m-tile, bh). 4 warps x 16 rows. BN=64 KV tiles.
// S = Qhi*Khi^T + Qhi*Klo^T (fp32 acc), online softmax, O += P(f16)*V(f16).
// ---------------------------------------------------------------------------
__global__ void __launch_bounds__(128, 1) attn_kernel(float* __restrict__ out)
{
    extern __shared__ char smem[];
    uint32_t sb = (uint32_t)__cvta_generic_to_shared(smem);
    int tid  = threadIdx.x;
    int lane = tid & 31;
    int w    = tid >> 5;
    int mt   = blockIdx.x;
    int bh   = blockIdx.y;
    int mi   = lane >> 3;   // ldmatrix sub-matrix index
    int li   = lane & 7;    // row within sub-matrix

    const __half* gQ  = g_Qh + ((size_t)bh * N_TOK + (size_t)mt * BM) * DIM;
    const __half* gK  = g_Kh + (size_t)bh * N_TOK * DIM;
    const __half* gKl = g_Kl + (size_t)bh * N_TOK * DIM;
    const __half* gV  = g_Vh + (size_t)bh * N_TOK * DIM;

    // group 0: Q tile + KV tile 0
#pragma unroll
    for (int it = 0; it < 16; it++) {
        int idx = tid + it * 128;
        int r = idx >> 5, c = idx & 31;
        cpasync16(swz(sb, r, c), gQ + r * DIM + c * 8);
    }
    load_kv(sb + SMEM_Q, gK, gKl, gV, 0, tid);
    asm volatile("cp.async.commit_group;\n" ::: "memory");
    // group 1: KV tile 1
    load_kv(sb + SMEM_Q + SMEM_BUF, gK, gKl, gV, 1, tid);
    asm volatile("cp.async.commit_group;\n" ::: "memory");

    float o[32][4];
#pragma unroll
    for (int u = 0; u < 32; u++) {
        o[u][0] = 0.f; o[u][1] = 0.f; o[u][2] = 0.f; o[u][3] = 0.f;
    }
    float M0 = -1e30f, M1 = -1e30f, l0 = 0.f, l1 = 0.f;
    const float SC = 0.09016844f;   // log2(e) / sqrt(256)

    // precomputed ldmatrix row indices
    int rA = 16 * w + (mi & 1) * 8 + li;          // Q A-frag rows (within CTA tile)
    int hiA = mi >> 1;                            // Q chunk offset
    int rB8 = (mi >> 1) * 8 + li;                 // K B-frag rows base
    int loB = mi & 1;                             // K chunk offset
    int rV8 = (mi & 1) * 8 + li;                  // V rows base
    int hiV = mi >> 1;                            // V chunk offset

    for (int t = 0; t < 16; t++) {
        asm volatile("cp.async.wait_group 1;\n" ::: "memory");
        __syncthreads();
        uint32_t kb = sb + SMEM_Q + (uint32_t)(t & 1) * SMEM_BUF;

        // ---- S = Q*Khi^T + Q*Klo^T  (raw, unscaled) ----
        float c[8][4];
#pragma unroll
        for (int j = 0; j < 8; j++) {
            c[j][0] = 0.f; c[j][1] = 0.f; c[j][2] = 0.f; c[j][3] = 0.f;
        }
#pragma unroll
        for (int ks = 0; ks < 16; ks++) {
            uint32_t a0, a1, a2, a3;
            ldsm4(a0, a1, a2, a3, swz(sb, rA, 2 * ks + hiA));
#pragma unroll
            for (int u = 0; u < 4; u++) {
                uint32_t b0, b1, b2, b3;
                ldsm4(b0, b1, b2, b3, swz(kb, 16 * u + rB8, 2 * ks + loB));
                mma16816(c[2 * u],     a0, a1, a2, a3, b0, b1);
                mma16816(c[2 * u + 1], a0, a1, a2, a3, b2, b3);
                ldsm4(b0, b1, b2, b3, swz(kb + 32768u, 16 * u + rB8, 2 * ks + loB));
                mma16816(c[2 * u],     a0, a1, a2, a3, b0, b1);
                mma16816(c[2 * u + 1], a0, a1, a2, a3, b2, b3);
            }
        }

        // ---- online softmax (rows: r0 = lane/4, r1 = lane/4 + 8) ----
        float mx0 = -1e30f, mx1 = -1e30f;
#pragma unroll
        for (int j = 0; j < 8; j++) {
            mx0 = fmaxf(mx0, fmaxf(c[j][0], c[j][1]));
            mx1 = fmaxf(mx1, fmaxf(c[j][2], c[j][3]));
        }
        mx0 = fmaxf(mx0, __shfl_xor_sync(0xffffffffu, mx0, 1));
        mx0 = fmaxf(mx0, __shfl_xor_sync(0xffffffffu, mx0, 2));
        mx1 = fmaxf(mx1, __shfl_xor_sync(0xffffffffu, mx1, 1));
        mx1 = fmaxf(mx1, __shfl_xor_sync(0xffffffffu, mx1, 2));
        float Mn0 = fmaxf(M0, mx0), Mn1 = fmaxf(M1, mx1);
        float s0 = ex2f((M0 - Mn0) * SC);
        float s1 = ex2f((M1 - Mn1) * SC);
        M0 = Mn0; M1 = Mn1;
        float ps0 = 0.f, ps1 = 0.f;
#pragma unroll
        for (int j = 0; j < 8; j++) {
            c[j][0] = ex2f((c[j][0] - Mn0) * SC); ps0 += c[j][0];
            c[j][1] = ex2f((c[j][1] - Mn0) * SC); ps0 += c[j][1];
            c[j][2] = ex2f((c[j][2] - Mn1) * SC); ps1 += c[j][2];
            c[j][3] = ex2f((c[j][3] - Mn1) * SC); ps1 += c[j][3];
        }
        l0 = l0 * s0 + ps0;
        l1 = l1 * s1 + ps1;
#pragma unroll
        for (int u = 0; u < 32; u++) {
            o[u][0] *= s0; o[u][1] *= s0; o[u][2] *= s1; o[u][3] *= s1;
        }

        // ---- O += P * V ----
        uint32_t vb = kb + 65536u;
#pragma unroll
        for (int s = 0; s < 4; s++) {
            uint32_t a0 = packh2(c[2 * s][0],     c[2 * s][1]);
            uint32_t a1 = packh2(c[2 * s][2],     c[2 * s][3]);
            uint32_t a2 = packh2(c[2 * s + 1][0], c[2 * s + 1][1]);
            uint32_t a3 = packh2(c[2 * s + 1][2], c[2 * s + 1][3]);
#pragma unroll
            for (int u = 0; u < 16; u++) {
                uint32_t b0, b1, b2, b3;
                ldsm4t(b0, b1, b2, b3, swz(vb, 16 * s + rV8, 2 * u + hiV));
                mma16816(o[2 * u],     a0, a1, a2, a3, b0, b1);
                mma16816(o[2 * u + 1], a0, a1, a2, a3, b2, b3);
            }
        }

        __syncthreads();   // all warps done reading buf (t&1)
        if (t + 2 < 16)
            load_kv(sb + SMEM_Q + (uint32_t)(t & 1) * SMEM_BUF, gK, gKl, gV, t + 2, tid);
        asm volatile("cp.async.commit_group;\n" ::: "memory");
    }

    // ---- epilogue: normalize and store fp32 ----
    l0 += __shfl_xor_sync(0xffffffffu, l0, 1);
    l0 += __shfl_xor_sync(0xffffffffu, l0, 2);
    l1 += __shfl_xor_sync(0xffffffffu, l1, 1);
    l1 += __shfl_xor_sync(0xffffffffu, l1, 2);
    float inv0 = 1.0f / l0;
    float inv1 = 1.0f / l1;

    int r0 = mt * BM + 16 * w + (lane >> 2);
    size_t ob = ((size_t)bh * N_TOK + r0) * DIM + 2 * (lane & 3);
#pragma unroll
    for (int u = 0; u < 32; u++) {
        float2 v0; v0.x = o[u][0] * inv0; v0.y = o[u][1] * inv0;
        float2 v1; v1.x = o[u][2] * inv1; v1.y = o[u][3] * inv1;
        *(float2*)(out + ob + u * 8)             = v0;
        *(float2*)(out + ob + 8 * DIM + u * 8)   = v1;
    }
}

// ---------------------------------------------------------------------------
extern "C" void kernel_launch(void* const* d_in, const int* in_sizes, int n_in,
                              void* d_out, int out_size) {
    const float* Q = (const float*)d_in[0];
    const float* K = (const float*)d_in[1];
    const float* V = (const float*)d_in[2];
    float* out = (float*)d_out;

    prep_kernel<<<NBH * N_TOK, 128>>>(Q, K, V);

    cudaFuncSetAttribute(attn_kernel,
                         cudaFuncAttributeMaxDynamicSharedMemorySize, SMEM_TOT);
    dim3 grid(N_TOK / BM, NBH);
    attn_kernel<<<grid, 128, SMEM_TOT>>>(out);
}

// round 3
// speedup vs baseline: 1.5052x; 1.5052x over previous
#include <cuda_runtime.h>
#include <cuda_fp16.h>
#include <stdint.h>
#include <math.h>

// Problem: B=8,H=8 (64 bh), N=1024 tokens, D=256. out fp32.
#define N_TOK 1024
#define DIM   256
#define NBH   64
#define BM    128
#define BN    64
#define TOT   (NBH * N_TOK * DIM)   // 16,777,216 elements

// fp16 scratch (device globals: allocation-free)
__device__ __half g_Qh[TOT];
__device__ __half g_Kh[TOT];
__device__ __half g_Vh[TOT];

// ---------------------------------------------------------------------------
// Preprocess: 2D RoPE on Q,K; convert all to fp16.
// One block per (bh*N + n) row; 128 threads = 128 complex pairs (D=256).
// ---------------------------------------------------------------------------
__global__ void __launch_bounds__(128) prep_kernel(
    const float* __restrict__ Q,
    const float* __restrict__ K,
    const float* __restrict__ V)
{
    int row = blockIdx.x;            // bh*1024 + n
    int i   = threadIdx.x;           // pair index 0..127
    int n   = row & (N_TOK - 1);
    // first 64 pairs use x = n%32, last 64 use y = n/32
    float pos = (i < 64) ? (float)(n & 31) : (float)(n >> 5);
    float e   = (float)(i & 63);
    // 10000^(-e/64) = 2^(-e * log2(10000)/64)
    float inv = exp2f(-0.20762050592445997f * e);
    float ang = pos * inv;           // in [0, 31]

    // range-reduce to [-pi, pi] (fast-math safe), then fast sincos
    float kq = rintf(ang * 0.15915494309189535f);
    float r  = fmaf(-kq, 6.2831854820251465f, ang);
    r        = fmaf(-kq, -1.7484555e-7f, r);
    float sa, ca;
    __sincosf(r, &sa, &ca);

    size_t base = (size_t)row * DIM + 2 * i;
    float2 q = *(const float2*)(Q + base);
    float2 k = *(const float2*)(K + base);
    float2 v = *(const float2*)(V + base);

    float q0 = q.x * ca - q.y * sa;
    float q1 = q.x * sa + q.y * ca;
    float k0 = k.x * ca - k.y * sa;
    float k1 = k.x * sa + k.y * ca;

    *(__half2*)(g_Qh + base) = __floats2half2_rn(q0, q1);
    *(__half2*)(g_Kh + base) = __floats2half2_rn(k0, k1);
    *(__half2*)(g_Vh + base) = __floats2half2_rn(v.x, v.y);
}

// ---------------------------------------------------------------------------
// PTX wrappers
// ---------------------------------------------------------------------------
__device__ __forceinline__ void ldsm4(uint32_t& r0, uint32_t& r1, uint32_t& r2,
                                      uint32_t& r3, uint32_t addr) {
    asm volatile("ldmatrix.sync.aligned.m8n8.x4.shared.b16 {%0,%1,%2,%3}, [%4];\n"
                 : "=r"(r0), "=r"(r1), "=r"(r2), "=r"(r3) : "r"(addr));
}
__device__ __forceinline__ void ldsm4t(uint32_t& r0, uint32_t& r1, uint32_t& r2,
                                       uint32_t& r3, uint32_t addr) {
    asm volatile("ldmatrix.sync.aligned.m8n8.x4.trans.shared.b16 {%0,%1,%2,%3}, [%4];\n"
                 : "=r"(r0), "=r"(r1), "=r"(r2), "=r"(r3) : "r"(addr));
}
__device__ __forceinline__ void mma16816(float* c,
                                         uint32_t a0, uint32_t a1, uint32_t a2, uint32_t a3,
                                         uint32_t b0, uint32_t b1) {
    asm volatile(
        "mma.sync.aligned.m16n8k16.row.col.f32.f16.f16.f32 "
        "{%0,%1,%2,%3},{%4,%5,%6,%7},{%8,%9},{%0,%1,%2,%3};\n"
        : "+f"(c[0]), "+f"(c[1]), "+f"(c[2]), "+f"(c[3])
        : "r"(a0), "r"(a1), "r"(a2), "r"(a3), "r"(b0), "r"(b1));
}
__device__ __forceinline__ void cpasync16(uint32_t sdst, const void* gsrc) {
    asm volatile("cp.async.cg.shared.global [%0], [%1], 16;\n"
                 :: "r"(sdst), "l"(gsrc) : "memory");
}
__device__ __forceinline__ float ex2f(float x) {
    float y;
    asm("ex2.approx.ftz.f32 %0, %1;" : "=f"(y) : "f"(x));
    return y;
}
__device__ __forceinline__ uint32_t packh2(float lo, float hi) {
    __half2 h = __floats2half2_rn(lo, hi);
    return *reinterpret_cast<uint32_t*>(&h);
}

// smem layout: Q tile 128x256 f16 (64 KB) + 2 buffers of {Khi,V} 64 KB each
#define SMEM_Q   65536u
#define SMEM_BUF 65536u
#define SMEM_TOT (SMEM_Q + 2u * SMEM_BUF)   // 196608

// XOR swizzle: rows are 512 B = 32 chunks of 16 B; phys chunk = c ^ (r&7)
__device__ __forceinline__ uint32_t swz(uint32_t base, int r, int c) {
    return base + ((uint32_t)r << 9) + (uint32_t)(((c ^ (r & 7))) << 4);
}

// Load one {Khi, V} 64x256 f16 tile pair into buffer at bb. 256 threads.
__device__ __forceinline__ void load_kv(uint32_t bb,
                                        const __half* __restrict__ gK,
                                        const __half* __restrict__ gV,
                                        int t, int tid) {
    int go0 = t * BN * DIM;
#pragma unroll
    for (int it = 0; it < 8; it++) {
        int idx = tid + it * 256;
        int r = idx >> 5, c = idx & 31;
        uint32_t so = ((uint32_t)r << 9) + (uint32_t)(((c ^ (r & 7))) << 4);
        int go = go0 + r * DIM + c * 8;
        cpasync16(bb + so,          gK + go);
        cpasync16(bb + 32768u + so, gV + go);
    }
}

// ---------------------------------------------------------------------------
// Flash attention: CTA = (m-tile of 128 rows, bh). 8 warps x 16 rows. BN=64.
// S = Q*K^T (f16 in, fp32 acc), online softmax, O += P(f16)*V(f16).
// ---------------------------------------------------------------------------
__global__ void __launch_bounds__(256, 1) attn_kernel(float* __restrict__ out)
{
    extern __shared__ char smem[];
    uint32_t sb = (uint32_t)__cvta_generic_to_shared(smem);
    int tid  = threadIdx.x;
    int lane = tid & 31;
    int w    = tid >> 5;            // 0..7
    int mt   = blockIdx.x;
    int bh   = blockIdx.y;
    int mi   = lane >> 3;   // ldmatrix sub-matrix index
    int li   = lane & 7;    // row within sub-matrix

    const __half* gQ = g_Qh + ((size_t)bh * N_TOK + (size_t)mt * BM) * DIM;
    const __half* gK = g_Kh + (size_t)bh * N_TOK * DIM;
    const __half* gV = g_Vh + (size_t)bh * N_TOK * DIM;

    // group 0: Q tile (128 rows x 32 chunks = 4096 chunks) + KV tile 0
#pragma unroll
    for (int it = 0; it < 16; it++) {
        int idx = tid + it * 256;
        int r = idx >> 5, c = idx & 31;
        cpasync16(swz(sb, r, c), gQ + r * DIM + c * 8);
    }
    load_kv(sb + SMEM_Q, gK, gV, 0, tid);
    asm volatile("cp.async.commit_group;\n" ::: "memory");
    // group 1: KV tile 1
    load_kv(sb + SMEM_Q + SMEM_BUF, gK, gV, 1, tid);
    asm volatile("cp.async.commit_group;\n" ::: "memory");

    float o[32][4];
#pragma unroll
    for (int u = 0; u < 32; u++) {
        o[u][0] = 0.f; o[u][1] = 0.f; o[u][2] = 0.f; o[u][3] = 0.f;
    }
    float M0 = -1e30f, M1 = -1e30f, l0 = 0.f, l1 = 0.f;
    const float SC = 0.09016844f;   // log2(e) / sqrt(256)

    // precomputed ldmatrix row indices
    int rA  = 16 * w + (mi & 1) * 8 + li;   // Q A-frag rows (within CTA tile)
    int hiA = mi >> 1;                      // Q chunk offset
    int rB8 = (mi >> 1) * 8 + li;           // K B-frag rows base
    int loB = mi & 1;                       // K chunk offset
    int rV8 = (mi & 1) * 8 + li;            // V rows base
    int hiV = mi >> 1;                      // V chunk offset

    for (int t = 0; t < 16; t++) {
        asm volatile("cp.async.wait_group 1;\n" ::: "memory");
        __syncthreads();
        uint32_t kb = sb + SMEM_Q + (uint32_t)(t & 1) * SMEM_BUF;

        // ---- S = Q*K^T  (raw, unscaled) ----
        float c[8][4];
#pragma unroll
        for (int j = 0; j < 8; j++) {
            c[j][0] = 0.f; c[j][1] = 0.f; c[j][2] = 0.f; c[j][3] = 0.f;
        }
#pragma unroll
        for (int ks = 0; ks < 16; ks++) {
            uint32_t a0, a1, a2, a3;
            ldsm4(a0, a1, a2, a3, swz(sb, rA, 2 * ks + hiA));
#pragma unroll
            for (int u = 0; u < 4; u++) {
                uint32_t b0, b1, b2, b3;
                ldsm4(b0, b1, b2, b3, swz(kb, 16 * u + rB8, 2 * ks + loB));
                mma16816(c[2 * u],     a0, a1, a2, a3, b0, b1);
                mma16816(c[2 * u + 1], a0, a1, a2, a3, b2, b3);
            }
        }

        // ---- online softmax (rows: r0 = lane/4, r1 = lane/4 + 8) ----
        float mx0 = -1e30f, mx1 = -1e30f;
#pragma unroll
        for (int j = 0; j < 8; j++) {
            mx0 = fmaxf(mx0, fmaxf(c[j][0], c[j][1]));
            mx1 = fmaxf(mx1, fmaxf(c[j][2], c[j][3]));
        }
        mx0 = fmaxf(mx0, __shfl_xor_sync(0xffffffffu, mx0, 1));
        mx0 = fmaxf(mx0, __shfl_xor_sync(0xffffffffu, mx0, 2));
        mx1 = fmaxf(mx1, __shfl_xor_sync(0xffffffffu, mx1, 1));
        mx1 = fmaxf(mx1, __shfl_xor_sync(0xffffffffu, mx1, 2));
        float Mn0 = fmaxf(M0, mx0), Mn1 = fmaxf(M1, mx1);
        float s0 = ex2f((M0 - Mn0) * SC);
        float s1 = ex2f((M1 - Mn1) * SC);
        M0 = Mn0; M1 = Mn1;
        float ps0 = 0.f, ps1 = 0.f;
#pragma unroll
        for (int j = 0; j < 8; j++) {
            c[j][0] = ex2f((c[j][0] - Mn0) * SC); ps0 += c[j][0];
            c[j][1] = ex2f((c[j][1] - Mn0) * SC); ps0 += c[j][1];
            c[j][2] = ex2f((c[j][2] - Mn1) * SC); ps1 += c[j][2];
            c[j][3] = ex2f((c[j][3] - Mn1) * SC); ps1 += c[j][3];
        }
        l0 = l0 * s0 + ps0;
        l1 = l1 * s1 + ps1;
#pragma unroll
        for (int u = 0; u < 32; u++) {
            o[u][0] *= s0; o[u][1] *= s0; o[u][2] *= s1; o[u][3] *= s1;
        }

        // ---- O += P * V ----
        uint32_t vb = kb + 32768u;
#pragma unroll
        for (int s = 0; s < 4; s++) {
            uint32_t a0 = packh2(c[2 * s][0],     c[2 * s][1]);
            uint32_t a1 = packh2(c[2 * s][2],     c[2 * s][3]);
            uint32_t a2 = packh2(c[2 * s + 1][0], c[2 * s + 1][1]);
            uint32_t a3 = packh2(c[2 * s + 1][2], c[2 * s + 1][3]);
#pragma unroll
            for (int u = 0; u < 16; u++) {
                uint32_t b0, b1, b2, b3;
                ldsm4t(b0, b1, b2, b3, swz(vb, 16 * s + rV8, 2 * u + hiV));
                mma16816(o[2 * u],     a0, a1, a2, a3, b0, b1);
                mma16816(o[2 * u + 1], a0, a1, a2, a3, b2, b3);
            }
        }

        __syncthreads();   // all warps done reading buf (t&1)
        if (t + 2 < 16)
            load_kv(sb + SMEM_Q + (uint32_t)(t & 1) * SMEM_BUF, gK, gV, t + 2, tid);
        asm volatile("cp.async.commit_group;\n" ::: "memory");
    }

    // ---- epilogue: normalize and store fp32 ----
    l0 += __shfl_xor_sync(0xffffffffu, l0, 1);
    l0 += __shfl_xor_sync(0xffffffffu, l0, 2);
    l1 += __shfl_xor_sync(0xffffffffu, l1, 1);
    l1 += __shfl_xor_sync(0xffffffffu, l1, 2);
    float inv0 = 1.0f / l0;
    float inv1 = 1.0f / l1;

    int r0 = mt * BM + 16 * w + (lane >> 2);
    size_t ob = ((size_t)bh * N_TOK + r0) * DIM + 2 * (lane & 3);
#pragma unroll
    for (int u = 0; u < 32; u++) {
        float2 v0; v0.x = o[u][0] * inv0; v0.y = o[u][1] * inv0;
        float2 v1; v1.x = o[u][2] * inv1; v1.y = o[u][3] * inv1;
        *(float2*)(out + ob + u * 8)             = v0;
        *(float2*)(out + ob + 8 * DIM + u * 8)   = v1;
    }
}

// ---------------------------------------------------------------------------
extern "C" void kernel_launch(void* const* d_in, const int* in_sizes, int n_in,
                              void* d_out, int out_size) {
    const float* Q = (const float*)d_in[0];
    const float* K = (const float*)d_in[1];
    const float* V = (const float*)d_in[2];
    float* out = (float*)d_out;

    prep_kernel<<<NBH * N_TOK, 128>>>(Q, K, V);

    cudaFuncSetAttribute(attn_kernel,
                         cudaFuncAttributeMaxDynamicSharedMemorySize, SMEM_TOT);
    dim3 grid(N_TOK / BM, NBH);
    attn_kernel<<<grid, 256, SMEM_TOT>>>(out);
}